// round 1
// baseline (speedup 1.0000x reference)
#include <cuda_runtime.h>
#include <math.h>
#include <stdint.h>

// ---------------------------------------------------------------------------
// TinyMoE: out = residual + shared_swiglu(x) @ Wd_s + sum_topk w_k * expert_k(x)
// T=4096 tokens, H=I=1024, E=8 experts, top-2 routing.
// Strategy: route first, compute only selected (token,expert) pairs.
// fp32 end-to-end (rel_err ~1e-6), packed f32x2 FMA microkernel.
// ---------------------------------------------------------------------------

#define T_TOK   4096
#define HD      1024
#define ID      1024
#define NE      8
#define PER_E   4096   // max tokens per expert (each token selects an expert at most once)

using ull = unsigned long long;

// ---- device scratch (allocation-free rule: static __device__ globals) ----
__device__ int   g_cnt[NE];
__device__ int   g_tok[NE][PER_E];
__device__ float g_wt [NE][PER_E];
__device__ float g_hid_s[(size_t)T_TOK * ID];            // shared-expert hidden
__device__ float g_hid_r[(size_t)NE * PER_E * ID];       // routed hidden (per expert, compacted)

// ---- packed f32x2 helpers (sm_103a) ----
__device__ __forceinline__ ull pack2(float lo, float hi) {
    ull r;
    asm("mov.b64 %0, {%1,%2};" : "=l"(r) : "r"(__float_as_uint(lo)), "r"(__float_as_uint(hi)));
    return r;
}
__device__ __forceinline__ void unpack2(ull v, float& lo, float& hi) {
    unsigned a, b;
    asm("mov.b64 {%0,%1}, %2;" : "=r"(a), "=r"(b) : "l"(v));
    lo = __uint_as_float(a); hi = __uint_as_float(b);
}
__device__ __forceinline__ ull fma2(ull a, ull b, ull c) {
    ull d;
    asm("fma.rn.f32x2 %0, %1, %2, %3;" : "=l"(d) : "l"(a), "l"(b), "l"(c));
    return d;
}

// ---------------------------------------------------------------------------
// init: zero per-expert counters
// ---------------------------------------------------------------------------
__global__ void k_init() {
    if (threadIdx.x < NE) g_cnt[threadIdx.x] = 0;
}

// ---------------------------------------------------------------------------
// router: one warp per token. 8 dot products over H, softmax, greedy top-2.
// Greedy argmax with strict '>' matches jax.lax.top_k tie-breaking (lowest idx).
// ---------------------------------------------------------------------------
__global__ void k_router(const float* __restrict__ X, const float* __restrict__ RW) {
    const int gwarp = (blockIdx.x * blockDim.x + threadIdx.x) >> 5;
    const int lane  = threadIdx.x & 31;
    if (gwarp >= T_TOK) return;

    const float* xr = X + (size_t)gwarp * HD;
    float acc[NE];
#pragma unroll
    for (int e = 0; e < NE; e++) acc[e] = 0.f;

    for (int h = lane; h < HD; h += 32) {
        const float xv = xr[h];
#pragma unroll
        for (int e = 0; e < NE; e++) acc[e] += xv * RW[e * HD + h];
    }
#pragma unroll
    for (int e = 0; e < NE; e++)
#pragma unroll
        for (int off = 16; off > 0; off >>= 1)
            acc[e] += __shfl_down_sync(0xffffffffu, acc[e], off);

    if (lane == 0) {
        float m = acc[0];
#pragma unroll
        for (int e = 1; e < NE; e++) m = fmaxf(m, acc[e]);
        float p[NE], s = 0.f;
#pragma unroll
        for (int e = 0; e < NE; e++) { p[e] = expf(acc[e] - m); s += p[e]; }
        const float inv = 1.f / s;
#pragma unroll
        for (int e = 0; e < NE; e++) p[e] *= inv;

        int   i1 = 0; float b1 = p[0];
#pragma unroll
        for (int e = 1; e < NE; e++) if (p[e] > b1) { b1 = p[e]; i1 = e; }
        int   i2 = -1; float b2 = -1.f;
#pragma unroll
        for (int e = 0; e < NE; e++) if (e != i1 && p[e] > b2) { b2 = p[e]; i2 = e; }

        int pos = atomicAdd(&g_cnt[i1], 1);
        g_tok[i1][pos] = gwarp; g_wt[i1][pos] = b1;  // routed_scaling_factor = 1
        pos = atomicAdd(&g_cnt[i2], 1);
        g_tok[i2][pos] = gwarp; g_wt[i2][pos] = b2;
    }
}

// ---------------------------------------------------------------------------
// Fused gate+up GEMM + SwiGLU: H = sigmoid(X@Wg) * (X@Wu)
// Tile 128x128, BK=8, 256 threads, 8x8 per thread, dual f32x2 accumulators.
// GATHER=true: rows gathered via g_tok[e], weights offset by expert,
//              output compacted into g_hid_r[e].
// ---------------------------------------------------------------------------
template<bool GATHER>
__global__ void __launch_bounds__(256, 1)
k_gateup(const float* __restrict__ X,
         const float* __restrict__ Wg_all,
         const float* __restrict__ Wu_all)
{
    constexpr int BM = 128, BN = 128, BK = 8;
    __shared__ float As[BK][BM];
    __shared__ float Bg[BK][BN];
    __shared__ float Bu[BK][BN];

    const int bn = blockIdx.x * BN;
    const int bm = blockIdx.y * BM;

    int nrows;
    const int*   toks = nullptr;
    const float *Wg, *Wu;
    float* Hout;
    if (GATHER) {
        const int e = blockIdx.z;
        nrows = g_cnt[e];
        if (bm >= nrows) return;
        toks = g_tok[e];
        Wg   = Wg_all + (size_t)e * HD * ID;
        Wu   = Wu_all + (size_t)e * HD * ID;
        Hout = g_hid_r + (size_t)e * PER_E * ID;
    } else {
        nrows = T_TOK;
        Wg = Wg_all; Wu = Wu_all;
        Hout = g_hid_s;
    }

    const int tid  = threadIdx.x;
    const int arow = tid >> 1,  acol = (tid & 1) * 4;
    const int brow = tid >> 5,  bcol = (tid & 31) * 4;
    const int tx   = tid & 15,  ty   = tid >> 4;

    int agrow;
    if (GATHER) {
        const int slot = bm + arow;
        agrow = (slot < nrows) ? toks[slot] : -1;
    } else {
        agrow = bm + arow;
    }

    ull accG[8][4], accU[8][4];
#pragma unroll
    for (int i = 0; i < 8; i++)
#pragma unroll
        for (int j = 0; j < 4; j++) { accG[i][j] = 0ull; accU[i][j] = 0ull; }

    for (int k0 = 0; k0 < HD; k0 += BK) {
        float4 av = make_float4(0.f, 0.f, 0.f, 0.f);
        if (agrow >= 0)
            av = *reinterpret_cast<const float4*>(X + (size_t)agrow * HD + k0 + acol);
        As[acol + 0][arow] = av.x;
        As[acol + 1][arow] = av.y;
        As[acol + 2][arow] = av.z;
        As[acol + 3][arow] = av.w;

        *reinterpret_cast<float4*>(&Bg[brow][bcol]) =
            *reinterpret_cast<const float4*>(Wg + (size_t)(k0 + brow) * ID + bn + bcol);
        *reinterpret_cast<float4*>(&Bu[brow][bcol]) =
            *reinterpret_cast<const float4*>(Wu + (size_t)(k0 + brow) * ID + bn + bcol);
        __syncthreads();

#pragma unroll
        for (int k = 0; k < BK; k++) {
            const float4 a0 = *reinterpret_cast<const float4*>(&As[k][ty * 8]);
            const float4 a1 = *reinterpret_cast<const float4*>(&As[k][ty * 8 + 4]);
            ull bg[4], bu[4];
#pragma unroll
            for (int j = 0; j < 4; j++) {
                bg[j] = *reinterpret_cast<const ull*>(&Bg[k][tx * 8 + 2 * j]);
                bu[j] = *reinterpret_cast<const ull*>(&Bu[k][tx * 8 + 2 * j]);
            }
            const float a_[8] = {a0.x, a0.y, a0.z, a0.w, a1.x, a1.y, a1.z, a1.w};
#pragma unroll
            for (int i = 0; i < 8; i++) {
                const ull a2 = pack2(a_[i], a_[i]);
#pragma unroll
                for (int j = 0; j < 4; j++) {
                    accG[i][j] = fma2(a2, bg[j], accG[i][j]);
                    accU[i][j] = fma2(a2, bu[j], accU[i][j]);
                }
            }
        }
        __syncthreads();
    }

    // epilogue: SwiGLU, store hidden
#pragma unroll
    for (int i = 0; i < 8; i++) {
        const int slot = bm + ty * 8 + i;
        if (GATHER && slot >= nrows) continue;
        float* hrow = Hout + (size_t)slot * ID + bn + tx * 8;
#pragma unroll
        for (int j = 0; j < 4; j++) {
            float g0, g1, u0, u1;
            unpack2(accG[i][j], g0, g1);
            unpack2(accU[i][j], u0, u1);
            float2 hv;
            hv.x = u0 / (1.f + expf(-g0));
            hv.y = u1 / (1.f + expf(-g1));
            *reinterpret_cast<float2*>(hrow + 2 * j) = hv;
        }
    }
}

// ---------------------------------------------------------------------------
// Down GEMM.
// SCATTER=false: out[t] = residual[t] + g_hid_s[t] @ Wd            (full write)
// SCATTER=true : atomicAdd(out[tok], w * (g_hid_r[e][slot] @ Wd_e)) (after dense)
// ---------------------------------------------------------------------------
template<bool SCATTER>
__global__ void __launch_bounds__(256, 1)
k_down(const float* __restrict__ Wd_all,
       const float* __restrict__ residual,
       float* __restrict__ out)
{
    constexpr int BM = 128, BN = 128, BK = 8;
    __shared__ float As[BK][BM];
    __shared__ float Bs[BK][BN];

    const int bn = blockIdx.x * BN;
    const int bm = blockIdx.y * BM;

    int nrows;
    const float* Hin;
    const float* Wd;
    const int*   toks = nullptr;
    const float* wts  = nullptr;
    if (SCATTER) {
        const int e = blockIdx.z;
        nrows = g_cnt[e];
        if (bm >= nrows) return;
        Hin  = g_hid_r + (size_t)e * PER_E * ID;
        Wd   = Wd_all + (size_t)e * ID * HD;
        toks = g_tok[e];
        wts  = g_wt[e];
    } else {
        nrows = T_TOK;
        Hin = g_hid_s;
        Wd  = Wd_all;
    }

    const int tid  = threadIdx.x;
    const int arow = tid >> 1,  acol = (tid & 1) * 4;
    const int brow = tid >> 5,  bcol = (tid & 31) * 4;
    const int tx   = tid & 15,  ty   = tid >> 4;

    const int aslot  = bm + arow;
    const bool avalid = (!SCATTER) || (aslot < nrows);

    ull acc[8][4];
#pragma unroll
    for (int i = 0; i < 8; i++)
#pragma unroll
        for (int j = 0; j < 4; j++) acc[i][j] = 0ull;

    for (int k0 = 0; k0 < ID; k0 += BK) {
        float4 av = make_float4(0.f, 0.f, 0.f, 0.f);
        if (avalid)
            av = *reinterpret_cast<const float4*>(Hin + (size_t)aslot * ID + k0 + acol);
        As[acol + 0][arow] = av.x;
        As[acol + 1][arow] = av.y;
        As[acol + 2][arow] = av.z;
        As[acol + 3][arow] = av.w;

        *reinterpret_cast<float4*>(&Bs[brow][bcol]) =
            *reinterpret_cast<const float4*>(Wd + (size_t)(k0 + brow) * HD + bn + bcol);
        __syncthreads();

#pragma unroll
        for (int k = 0; k < BK; k++) {
            const float4 a0 = *reinterpret_cast<const float4*>(&As[k][ty * 8]);
            const float4 a1 = *reinterpret_cast<const float4*>(&As[k][ty * 8 + 4]);
            ull bb[4];
#pragma unroll
            for (int j = 0; j < 4; j++)
                bb[j] = *reinterpret_cast<const ull*>(&Bs[k][tx * 8 + 2 * j]);
            const float a_[8] = {a0.x, a0.y, a0.z, a0.w, a1.x, a1.y, a1.z, a1.w};
#pragma unroll
            for (int i = 0; i < 8; i++) {
                const ull a2 = pack2(a_[i], a_[i]);
#pragma unroll
                for (int j = 0; j < 4; j++)
                    acc[i][j] = fma2(a2, bb[j], acc[i][j]);
            }
        }
        __syncthreads();
    }

#pragma unroll
    for (int i = 0; i < 8; i++) {
        const int slot = bm + ty * 8 + i;
        if (SCATTER) {
            if (slot >= nrows) continue;
            const int   t = toks[slot];
            const float w = wts[slot];
            float* ob = out + (size_t)t * HD + bn + tx * 8;
#pragma unroll
            for (int j = 0; j < 4; j++) {
                float lo, hi;
                unpack2(acc[i][j], lo, hi);
                atomicAdd(ob + 2 * j,     w * lo);
                atomicAdd(ob + 2 * j + 1, w * hi);
            }
        } else {
            const float* rb = residual + (size_t)slot * HD + bn + tx * 8;
            float*       ob = out      + (size_t)slot * HD + bn + tx * 8;
#pragma unroll
            for (int j = 0; j < 4; j++) {
                float lo, hi;
                unpack2(acc[i][j], lo, hi);
                const float2 rv = *reinterpret_cast<const float2*>(rb + 2 * j);
                float2 ov;
                ov.x = rv.x + lo;
                ov.y = rv.y + hi;
                *reinterpret_cast<float2*>(ob + 2 * j) = ov;
            }
        }
    }
}

// ---------------------------------------------------------------------------
// launch
// ---------------------------------------------------------------------------
extern "C" void kernel_launch(void* const* d_in, const int* in_sizes, int n_in,
                              void* d_out, int out_size)
{
    const float* X  = (const float*)d_in[0];   // hidden_states [T, H]
    const float* RW = (const float*)d_in[1];   // router_w [E, H]
    const float* SG = (const float*)d_in[2];   // shared_gate [H, I]
    const float* SU = (const float*)d_in[3];   // shared_up   [H, I]
    const float* SD = (const float*)d_in[4];   // shared_down [I, H]
    const float* EG = (const float*)d_in[5];   // experts_gate [E, H, I]
    const float* EU = (const float*)d_in[6];   // experts_up   [E, H, I]
    const float* ED = (const float*)d_in[7];   // experts_down [E, I, H]
    float* out = (float*)d_out;

    k_init<<<1, 32>>>();
    k_router<<<T_TOK / 4, 128>>>(X, RW);

    // shared expert gate+up (dense)
    k_gateup<false><<<dim3(ID / 128, T_TOK / 128, 1), 256>>>(X, SG, SU);
    // routed experts gate+up (gathered; worst-case grid, early exit)
    k_gateup<true ><<<dim3(ID / 128, PER_E / 128, NE), 256>>>(X, EG, EU);

    // shared down: writes out = residual + shared_out  (full coverage)
    k_down<false><<<dim3(HD / 128, T_TOK / 128, 1), 256>>>(SD, X, out);
    // routed down: atomicAdd of weighted expert outputs
    k_down<true ><<<dim3(HD / 128, PER_E / 128, NE), 256>>>(ED, X, out);
}